// round 4
// baseline (speedup 1.0000x reference)
#include <cuda_runtime.h>
#include <cuda_bf16.h>

// Model: x[n,t,:] = [features[n,0..11], AVG[t]]  (T=120, F=13)
// h1 = LSTM(H=30)(x);  out = LSTM(H=1)(h1)
// Decomposition: one warp per sequence.
//   lane u in [0,30): owns hidden unit u of LSTM1; holds W_hh1 rows {u, 30+u, 60+u, 90+u} in registers.
//   lane 30: holds W_ih2 rows {0..3} in the same register slots, so the shared k-loop
//            (shfl-broadcast of h1) simultaneously produces LSTM2's input dots.
//   lane 31: zero weights (idle).

#define TT   120
#define HH   30
#define FEAT 12

__constant__ float AVG_c[TT] = {
    0.0256f,0.0823f,0.1157f,0.1315f,0.1366f,0.1369f,0.1347f,0.1308f,0.1259f,0.1205f,
    0.1146f,0.1086f,0.1028f,0.0970f,0.0913f,0.0858f,0.0805f,0.0756f,0.0708f,0.0664f,
    0.0623f,0.0584f,0.0549f,0.0515f,0.0485f,0.0456f,0.0429f,0.0404f,0.0381f,0.0360f,
    0.0340f,0.0321f,0.0304f,0.0287f,0.0272f,0.0258f,0.0245f,0.0233f,0.0222f,0.0211f,
    0.0201f,0.0191f,0.0182f,0.0173f,0.0165f,0.0158f,0.0150f,0.0143f,0.0137f,0.0130f,
    0.0125f,0.0119f,0.0114f,0.0108f,0.0104f,0.0099f,0.0095f,0.0091f,0.0087f,0.0083f,
    0.0080f,0.0077f,0.0074f,0.0071f,0.0068f,0.0065f,0.0062f,0.0060f,0.0058f,0.0055f,
    0.0053f,0.0050f,0.0049f,0.0047f,0.0045f,0.0044f,0.0042f,0.0040f,0.0039f,0.0038f,
    0.0036f,0.0034f,0.0033f,0.0032f,0.0031f,0.0030f,0.0029f,0.0028f,0.0027f,0.0026f,
    0.0025f,0.0024f,0.0023f,0.0022f,0.0021f,0.0021f,0.0020f,0.0019f,0.0018f,0.0018f,
    0.0017f,0.0017f,0.0016f,0.0016f,0.0015f,0.0015f,0.0014f,0.0014f,0.0013f,0.0013f,
    0.0013f,0.0012f,0.0012f,0.0011f,0.0011f,0.0011f,0.0010f,0.0010f,0.0010f,0.0009f
};

__device__ __forceinline__ float sigmoid_f(float x) {
    // 1/(1+e^-x): EX2 + RCP, ~1e-6 rel err
    float e = __expf(-x);
    return __fdividef(1.0f, 1.0f + e);
}
__device__ __forceinline__ float tanh_f(float x) {
    // 1 - 2/(1+e^{2x}); well-behaved at both extremes and near 0
    float e = __expf(2.0f * x);
    return 1.0f - __fdividef(2.0f, 1.0f + e);
}

__global__ __launch_bounds__(256)
void lstm_trace_kernel(const float* __restrict__ features,
                       const float* __restrict__ w_ih1,   // [120,13]
                       const float* __restrict__ w_hh1,   // [120,30]
                       const float* __restrict__ b1,      // [120]
                       const float* __restrict__ w_ih2,   // [4,30]
                       const float* __restrict__ w_hh2,   // [4,1]
                       const float* __restrict__ b2,      // [4]
                       float* __restrict__ out,           // [N,120]
                       int N)
{
    const int warp_id = (blockIdx.x * blockDim.x + threadIdx.x) >> 5;
    const int lane    = threadIdx.x & 31;
    if (warp_id >= N) return;

    const float* feat = features + warp_id * FEAT;

    // ---- per-lane weights in registers ----
    float wi[HH], wf[HH], wg[HH], wo[HH];
    float base_i = 0.f, base_f = 0.f, base_g = 0.f, base_o = 0.f;
    float w12_i = 0.f, w12_f = 0.f, w12_g = 0.f, w12_o = 0.f;

    if (lane < HH) {
        const float* ri = w_hh1 + (0 * HH + lane) * HH;
        const float* rf = w_hh1 + (1 * HH + lane) * HH;
        const float* rg = w_hh1 + (2 * HH + lane) * HH;
        const float* ro = w_hh1 + (3 * HH + lane) * HH;
        #pragma unroll
        for (int k = 0; k < HH; k++) {
            wi[k] = ri[k]; wf[k] = rf[k]; wg[k] = rg[k]; wo[k] = ro[k];
        }
        const float* pi = w_ih1 + (0 * HH + lane) * (FEAT + 1);
        const float* pf = w_ih1 + (1 * HH + lane) * (FEAT + 1);
        const float* pg = w_ih1 + (2 * HH + lane) * (FEAT + 1);
        const float* po = w_ih1 + (3 * HH + lane) * (FEAT + 1);
        base_i = b1[0 * HH + lane];
        base_f = b1[1 * HH + lane];
        base_g = b1[2 * HH + lane];
        base_o = b1[3 * HH + lane];
        #pragma unroll
        for (int d = 0; d < FEAT; d++) {
            float fd = feat[d];
            base_i = fmaf(fd, pi[d], base_i);
            base_f = fmaf(fd, pf[d], base_f);
            base_g = fmaf(fd, pg[d], base_g);
            base_o = fmaf(fd, po[d], base_o);
        }
        w12_i = pi[FEAT]; w12_f = pf[FEAT]; w12_g = pg[FEAT]; w12_o = po[FEAT];
    } else if (lane == HH) {
        // LSTM2 input weights ride in the same accumulator slots
        #pragma unroll
        for (int k = 0; k < HH; k++) {
            wi[k] = w_ih2[0 * HH + k];
            wf[k] = w_ih2[1 * HH + k];
            wg[k] = w_ih2[2 * HH + k];
            wo[k] = w_ih2[3 * HH + k];
        }
    } else {
        #pragma unroll
        for (int k = 0; k < HH; k++) { wi[k] = wf[k] = wg[k] = wo[k] = 0.f; }
    }

    // LSTM2 scalar params (uniform loads, all lanes)
    float wh2_0 = w_hh2[0], wh2_1 = w_hh2[1], wh2_2 = w_hh2[2], wh2_3 = w_hh2[3];
    float b2_0 = b2[0], b2_1 = b2[1], b2_2 = b2[2], b2_3 = b2[3];

    float h1 = 0.f, c1 = 0.f;   // lane u: LSTM1 state of unit u
    float h2 = 0.f, c2 = 0.f;   // valid in lane 30 only
    float* outp = out + warp_id * TT;

    #pragma unroll 1
    for (int t = 0; t < TT; t++) {
        const float at = AVG_c[t];
        float gi = fmaf(at, w12_i, base_i);
        float gf = fmaf(at, w12_f, base_f);
        float gg = fmaf(at, w12_g, base_g);
        float go = fmaf(at, w12_o, base_o);
        #pragma unroll
        for (int k = 0; k < HH; k++) {
            float hk = __shfl_sync(0xffffffffu, h1, k);  // h1[t-1][k]
            gi = fmaf(hk, wi[k], gi);
            gf = fmaf(hk, wf[k], gf);
            gg = fmaf(hk, wg[k], gg);
            go = fmaf(hk, wo[k], go);
        }
        // ---- LSTM2 step (t-1): lane 30's gi..go are its input dots of h1[t-1] ----
        if (t > 0) {
            float a2i = gi + fmaf(wh2_0, h2, b2_0);
            float a2f = gf + fmaf(wh2_1, h2, b2_1);
            float a2g = gg + fmaf(wh2_2, h2, b2_2);
            float a2o = go + fmaf(wh2_3, h2, b2_3);
            c2 = sigmoid_f(a2f) * c2 + sigmoid_f(a2i) * tanh_f(a2g);
            h2 = sigmoid_f(a2o) * tanh_f(c2);
            if (lane == HH) outp[t - 1] = h2;
        }
        // ---- LSTM1 update for step t (lanes < 30; garbage elsewhere, never read) ----
        float si = sigmoid_f(gi);
        float sf = sigmoid_f(gf);
        float sg = tanh_f(gg);
        float so = sigmoid_f(go);
        c1 = sf * c1 + si * sg;
        h1 = so * tanh_f(c1);
    }

    // ---- epilogue: LSTM2 step 119 using h1[119] ----
    {
        float gi = 0.f, gf = 0.f, gg = 0.f, go = 0.f;
        #pragma unroll
        for (int k = 0; k < HH; k++) {
            float hk = __shfl_sync(0xffffffffu, h1, k);
            gi = fmaf(hk, wi[k], gi);
            gf = fmaf(hk, wf[k], gf);
            gg = fmaf(hk, wg[k], gg);
            go = fmaf(hk, wo[k], go);
        }
        float a2i = gi + fmaf(wh2_0, h2, b2_0);
        float a2f = gf + fmaf(wh2_1, h2, b2_1);
        float a2g = gg + fmaf(wh2_2, h2, b2_2);
        float a2o = go + fmaf(wh2_3, h2, b2_3);
        c2 = sigmoid_f(a2f) * c2 + sigmoid_f(a2i) * tanh_f(a2g);
        h2 = sigmoid_f(a2o) * tanh_f(c2);
        if (lane == HH) outp[TT - 1] = h2;
    }
}

extern "C" void kernel_launch(void* const* d_in, const int* in_sizes, int n_in,
                              void* d_out, int out_size) {
    const float* features = (const float*)d_in[0];
    const float* w_ih1    = (const float*)d_in[1];
    const float* w_hh1    = (const float*)d_in[2];
    const float* b1       = (const float*)d_in[3];
    const float* w_ih2    = (const float*)d_in[4];
    const float* w_hh2    = (const float*)d_in[5];
    const float* b2       = (const float*)d_in[6];
    float* out = (float*)d_out;

    const int N = in_sizes[0] / FEAT;           // 32768
    const int threads = 256;                    // 8 warps/block, 1 warp = 1 sequence
    const int blocks  = (N * 32 + threads - 1) / threads;

    lstm_trace_kernel<<<blocks, threads>>>(features, w_ih1, w_hh1, b1,
                                           w_ih2, w_hh2, b2, out, N);
}

// round 7
// speedup vs baseline: 1.2595x; 1.2595x over previous
#include <cuda_runtime.h>
#include <cuda_bf16.h>

// Model: x[n,t,:] = [features[n,0..11], AVG[t]]  (T=120, F=13)
// h1 = LSTM(H=30)(x);  out = LSTM(H=1)(h1)
// One warp per sequence; lane u<30 owns hidden unit u (4 gate rows in regs,
// packed as f32x2 pairs (i,f) and (g,o)); lane 30 carries the W_ih2 rows so
// the shared shfl/FFMA2 k-loop also produces LSTM2's input dots.
// Inner loop uses sm_103a packed fma.rn.f32x2 (2 FMAs per issue).

#define TT   120
#define HH   30
#define FEAT 12

typedef unsigned long long u64;

__constant__ float AVG_c[TT] = {
    0.0256f,0.0823f,0.1157f,0.1315f,0.1366f,0.1369f,0.1347f,0.1308f,0.1259f,0.1205f,
    0.1146f,0.1086f,0.1028f,0.0970f,0.0913f,0.0858f,0.0805f,0.0756f,0.0708f,0.0664f,
    0.0623f,0.0584f,0.0549f,0.0515f,0.0485f,0.0456f,0.0429f,0.0404f,0.0381f,0.0360f,
    0.0340f,0.0321f,0.0304f,0.0287f,0.0272f,0.0258f,0.0245f,0.0233f,0.0222f,0.0211f,
    0.0201f,0.0191f,0.0182f,0.0173f,0.0165f,0.0158f,0.0150f,0.0143f,0.0137f,0.0130f,
    0.0125f,0.0119f,0.0114f,0.0108f,0.0104f,0.0099f,0.0095f,0.0091f,0.0087f,0.0083f,
    0.0080f,0.0077f,0.0074f,0.0071f,0.0068f,0.0065f,0.0062f,0.0060f,0.0058f,0.0055f,
    0.0053f,0.0050f,0.0049f,0.0047f,0.0045f,0.0044f,0.0042f,0.0040f,0.0039f,0.0038f,
    0.0036f,0.0034f,0.0033f,0.0032f,0.0031f,0.0030f,0.0029f,0.0028f,0.0027f,0.0026f,
    0.0025f,0.0024f,0.0023f,0.0022f,0.0021f,0.0021f,0.0020f,0.0019f,0.0018f,0.0018f,
    0.0017f,0.0017f,0.0016f,0.0016f,0.0015f,0.0015f,0.0014f,0.0014f,0.0013f,0.0013f,
    0.0013f,0.0012f,0.0012f,0.0011f,0.0011f,0.0011f,0.0010f,0.0010f,0.0010f,0.0009f
};

// ---- packed f32x2 helpers (Blackwell) ----
__device__ __forceinline__ u64 pack2(float lo, float hi) {
    u64 d; asm("mov.b64 %0, {%1, %2};" : "=l"(d) : "f"(lo), "f"(hi)); return d;
}
__device__ __forceinline__ u64 pack2_dup(float x) {
    u64 d; asm("mov.b64 %0, {%1, %1};" : "=l"(d) : "f"(x)); return d;
}
__device__ __forceinline__ void unpack2(u64 v, float& lo, float& hi) {
    asm("mov.b64 {%0, %1}, %2;" : "=f"(lo), "=f"(hi) : "l"(v));
}
__device__ __forceinline__ u64 fma2(u64 a, u64 b, u64 c) {
    u64 d; asm("fma.rn.f32x2 %0, %1, %2, %3;" : "=l"(d) : "l"(a), "l"(b), "l"(c)); return d;
}
__device__ __forceinline__ u64 add2(u64 a, u64 b) {
    u64 d; asm("add.rn.f32x2 %0, %1, %2;" : "=l"(d) : "l"(a), "l"(b)); return d;
}

__device__ __forceinline__ float sigmoid_f(float x) {
    float e = __expf(-x);
    return __fdividef(1.0f, 1.0f + e);
}
__device__ __forceinline__ float tanh_f(float x) {
    float e = __expf(2.0f * x);
    return 1.0f - __fdividef(2.0f, 1.0f + e);
}

__global__ __launch_bounds__(128, 3)
void lstm_trace_kernel(const float* __restrict__ features,
                       const float* __restrict__ w_ih1,   // [120,13]
                       const float* __restrict__ w_hh1,   // [120,30]
                       const float* __restrict__ b1,      // [120]
                       const float* __restrict__ w_ih2,   // [4,30]
                       const float* __restrict__ w_hh2,   // [4,1]
                       const float* __restrict__ b2,      // [4]
                       float* __restrict__ out,           // [N,120]
                       int N)
{
    const int warp_id = (blockIdx.x * blockDim.x + threadIdx.x) >> 5;
    const int lane    = threadIdx.x & 31;
    if (warp_id >= N) return;

    const float* feat = features + warp_id * FEAT;

    // ---- per-lane packed weights: wif[k] = {W_i[k], W_f[k]}, wgo[k] = {W_g[k], W_o[k]} ----
    u64 wif[HH], wgo[HH];
    u64 base_if = 0ull, base_go = 0ull;   // packed {base_i, base_f}, {base_g, base_o}
    u64 w12_if  = 0ull, w12_go  = 0ull;   // packed trace-channel weights

    if (lane < HH) {
        const float* ri = w_hh1 + (0 * HH + lane) * HH;
        const float* rf = w_hh1 + (1 * HH + lane) * HH;
        const float* rg = w_hh1 + (2 * HH + lane) * HH;
        const float* ro = w_hh1 + (3 * HH + lane) * HH;
        #pragma unroll
        for (int k = 0; k < HH; k++) {
            wif[k] = pack2(ri[k], rf[k]);
            wgo[k] = pack2(rg[k], ro[k]);
        }
        const float* pi = w_ih1 + (0 * HH + lane) * (FEAT + 1);
        const float* pf = w_ih1 + (1 * HH + lane) * (FEAT + 1);
        const float* pg = w_ih1 + (2 * HH + lane) * (FEAT + 1);
        const float* po = w_ih1 + (3 * HH + lane) * (FEAT + 1);
        float base_i = b1[0 * HH + lane];
        float base_f = b1[1 * HH + lane];
        float base_g = b1[2 * HH + lane];
        float base_o = b1[3 * HH + lane];
        #pragma unroll
        for (int d = 0; d < FEAT; d++) {
            float fd = feat[d];
            base_i = fmaf(fd, pi[d], base_i);
            base_f = fmaf(fd, pf[d], base_f);
            base_g = fmaf(fd, pg[d], base_g);
            base_o = fmaf(fd, po[d], base_o);
        }
        base_if = pack2(base_i, base_f);
        base_go = pack2(base_g, base_o);
        w12_if  = pack2(pi[FEAT], pf[FEAT]);
        w12_go  = pack2(pg[FEAT], po[FEAT]);
    } else if (lane == HH) {
        // LSTM2 input weights ride in the same accumulator slots
        #pragma unroll
        for (int k = 0; k < HH; k++) {
            wif[k] = pack2(w_ih2[0 * HH + k], w_ih2[1 * HH + k]);
            wgo[k] = pack2(w_ih2[2 * HH + k], w_ih2[3 * HH + k]);
        }
    } else {
        #pragma unroll
        for (int k = 0; k < HH; k++) { wif[k] = 0ull; wgo[k] = 0ull; }
    }

    // LSTM2 scalar params (uniform loads, all lanes)
    float wh2_0 = w_hh2[0], wh2_1 = w_hh2[1], wh2_2 = w_hh2[2], wh2_3 = w_hh2[3];
    float b2_0 = b2[0], b2_1 = b2[1], b2_2 = b2[2], b2_3 = b2[3];

    float h1v = 0.f, c1 = 0.f;   // lane u: LSTM1 state of unit u
    float h2 = 0.f, c2 = 0.f;    // valid in lane 30 only
    float* outp = out + warp_id * TT;

    #pragma unroll 1
    for (int t = 0; t < TT; t++) {
        const u64 at2 = pack2_dup(AVG_c[t]);
        // dual accumulators per packed pair -> 4 independent FFMA2 chains
        u64 aif0 = fma2(at2, w12_if, base_if);
        u64 ago0 = fma2(at2, w12_go, base_go);
        u64 aif1 = 0ull, ago1 = 0ull;
        #pragma unroll
        for (int k = 0; k < HH; k += 2) {
            u64 h0 = pack2_dup(__shfl_sync(0xffffffffu, h1v, k));
            aif0 = fma2(h0, wif[k], aif0);
            ago0 = fma2(h0, wgo[k], ago0);
            u64 hb = pack2_dup(__shfl_sync(0xffffffffu, h1v, k + 1));
            aif1 = fma2(hb, wif[k + 1], aif1);
            ago1 = fma2(hb, wgo[k + 1], ago1);
        }
        float gi, gf, gg, go;
        unpack2(add2(aif0, aif1), gi, gf);
        unpack2(add2(ago0, ago1), gg, go);

        // ---- LSTM2 step (t-1): lane 30's gi..go are its input dots of h1[t-1] ----
        if (t > 0) {
            float a2i = gi + fmaf(wh2_0, h2, b2_0);
            float a2f = gf + fmaf(wh2_1, h2, b2_1);
            float a2g = gg + fmaf(wh2_2, h2, b2_2);
            float a2o = go + fmaf(wh2_3, h2, b2_3);
            c2 = sigmoid_f(a2f) * c2 + sigmoid_f(a2i) * tanh_f(a2g);
            h2 = sigmoid_f(a2o) * tanh_f(c2);
            if (lane == HH) outp[t - 1] = h2;
        }
        // ---- LSTM1 update for step t (lanes < 30; garbage elsewhere, never read) ----
        float si = sigmoid_f(gi);
        float sf = sigmoid_f(gf);
        float sg = tanh_f(gg);
        float so = sigmoid_f(go);
        c1 = sf * c1 + si * sg;
        h1v = so * tanh_f(c1);
    }

    // ---- epilogue: LSTM2 step 119 using h1[119] ----
    {
        u64 aif0 = 0ull, ago0 = 0ull, aif1 = 0ull, ago1 = 0ull;
        #pragma unroll
        for (int k = 0; k < HH; k += 2) {
            u64 h0 = pack2_dup(__shfl_sync(0xffffffffu, h1v, k));
            aif0 = fma2(h0, wif[k], aif0);
            ago0 = fma2(h0, wgo[k], ago0);
            u64 hb = pack2_dup(__shfl_sync(0xffffffffu, h1v, k + 1));
            aif1 = fma2(hb, wif[k + 1], aif1);
            ago1 = fma2(hb, wgo[k + 1], ago1);
        }
        float gi, gf, gg, go;
        unpack2(add2(aif0, aif1), gi, gf);
        unpack2(add2(ago0, ago1), gg, go);
        float a2i = gi + fmaf(wh2_0, h2, b2_0);
        float a2f = gf + fmaf(wh2_1, h2, b2_1);
        float a2g = gg + fmaf(wh2_2, h2, b2_2);
        float a2o = go + fmaf(wh2_3, h2, b2_3);
        c2 = sigmoid_f(a2f) * c2 + sigmoid_f(a2i) * tanh_f(a2g);
        h2 = sigmoid_f(a2o) * tanh_f(c2);
        if (lane == HH) outp[TT - 1] = h2;
    }
}

extern "C" void kernel_launch(void* const* d_in, const int* in_sizes, int n_in,
                              void* d_out, int out_size) {
    const float* features = (const float*)d_in[0];
    const float* w_ih1    = (const float*)d_in[1];
    const float* w_hh1    = (const float*)d_in[2];
    const float* b1       = (const float*)d_in[3];
    const float* w_ih2    = (const float*)d_in[4];
    const float* w_hh2    = (const float*)d_in[5];
    const float* b2       = (const float*)d_in[6];
    float* out = (float*)d_out;

    const int N = in_sizes[0] / FEAT;           // 32768
    const int threads = 128;                    // 4 warps/block -> 3 CTAs/SM (12 warps)
    const int blocks  = (N * 32 + threads - 1) / threads;

    lstm_trace_kernel<<<blocks, threads>>>(features, w_ih1, w_hh1, b1,
                                           w_ih2, w_hh2, b2, out, N);
}